// round 8
// baseline (speedup 1.0000x reference)
#include <cuda_runtime.h>

#define Bc 16
#define Sc 512
#define Dc 768
#define Lc 20
#define INNERc 64
#define NPROJ 168          // 128 (w1) + 40 (w2)
#define WS_STRIDE 192      // padded so col pairs up to 190 stay in bounds
#define ROWS (Bc*Sc)       // 8192
#define NEGV 1000000000000.0f
#define NTOT (Bc*Lc*Sc*Sc) // 83886080

// scratch (no allocation allowed -> __device__ globals)
__device__ float g_q[ROWS * INNERc];     // rope'd q
__device__ float g_k[ROWS * INNERc];     // rope'd k
__device__ float g_d[ROWS * 40];         // (x@w2+b2)/2

// ---------------------------------------------------------------------------
// Kernel 1: projection GEMM (packed f32x2 FMA) + fused trig + RoPE epilogue.
//
// 32 rows/block, K=768 in 32-chunks. Each lane owns column PAIRS
// (2*lane + 64*cp, cp<3): ws read as LDS.64, accumulation via PTX
// fma.rn.f32x2 (FFMA2: 2 fp32 FMAs per issue slot; IEEE-rn per element,
// bit-identical to fmaf). x values are stored PRE-SPLATTED in smem as
// duplicated float2, so the packed multiplier is a single LDS.64 broadcast
// (no per-iteration mov.b64 splats). cp=2 pairs for lane>=20 read padded
// garbage and are never stored.
//
// Trig per block: warp-0 lanes do the fp64 exp/log for the 32 freqs once;
// all threads range-reduce (5 fp64 ops) + sinf/cosf into an smem table used
// by the RoPE epilogue. No separate trig kernel.
// ---------------------------------------------------------------------------
#define XS2_STRIDE 33                        // float2 stride
#define PS_STRIDE 172
#define WS_OFF   (32*XS2_STRIDE*2)           // 2112 floats
#define POOL_FLOATS (WS_OFF + 32*WS_STRIDE)  // 8256 >= 32*172 = 5504

__global__ __launch_bounds__(256) void proj_rope_kernel(
    const float* __restrict__ x,
    const float* __restrict__ w1, const float* __restrict__ b1,
    const float* __restrict__ w2, const float* __restrict__ b2)
{
    __shared__ __align__(16) float pool[POOL_FLOATS];
    __shared__ float  sfreq[32];
    __shared__ float2 strig[1024];           // [r<<5 | i] for this block's rows
    float2 (*xs2)[XS2_STRIDE] = (float2(*)[XS2_STRIDE])pool;        // pre-splatted x
    float  (*ws)[WS_STRIDE]   = (float(*)[WS_STRIDE])(pool + WS_OFF);
    float  (*ps)[PS_STRIDE]   = (float(*)[PS_STRIDE])pool;          // aliases xs2/ws

    const int t    = threadIdx.x;
    const int lane = t & 31;
    const int warp = t >> 5;
    const int row0 = blockIdx.x * 32;
    const int co0  = 2 * lane;

    // --- trig table for this block (rows row0..row0+31) ---
    if (t < 32)
        sfreq[t] = (float)exp(-2.0 * (double)t / 64.0 * log(10000.0));
    __syncthreads();
#pragma unroll
    for (int it = 0; it < 4; it++) {
        int f = t + it * 256;
        int r = f >> 5, i = f & 31;
        int s = (row0 + r) & (Sc - 1);
        float ang = (float)s * sfreq[i];     // fp32 rounding as in reference
        double a  = (double)ang;
        double q  = floor(a * 0.15915494309189535);   // 1/(2*pi)
        double rr = a - 6.283185307179586 * q;
        if (rr > 3.141592653589793) rr -= 6.283185307179586;
        float rf = (float)rr;
        strig[f] = make_float2(sinf(rf), cosf(rf));
    }

    // --- GEMM mainloop ---
    unsigned long long acc2[4][3];
#pragma unroll
    for (int i = 0; i < 4; i++)
#pragma unroll
        for (int c = 0; c < 3; c++) acc2[i][c] = 0ull;

    for (int k0 = 0; k0 < Dc; k0 += 32) {
#pragma unroll
        for (int i = 0; i < 4; i++) {
            int f = t + i * 256;
            int r = f >> 5, kk = f & 31;
            float v = x[(row0 + r) * Dc + k0 + kk];
            xs2[r][kk] = make_float2(v, v);          // pre-splatted (STS.64)
        }
#pragma unroll
        for (int i = 0; i < 16; i++) {
            int f = t + i * 256;
            int kk = f >> 7, n = f & 127;
            ws[kk][n] = w1[(k0 + kk) * 128 + n];
        }
#pragma unroll
        for (int i = 0; i < 5; i++) {
            int f = t + i * 256;
            if (f < 32 * 40) {
                int kk = f / 40, n = f % 40;
                ws[kk][128 + n] = w2[(k0 + kk) * 40 + n];
            }
        }
        __syncthreads();
#pragma unroll 4
        for (int kk = 0; kk < 32; kk++) {
            unsigned long long w0 = *(const unsigned long long*)&ws[kk][co0];
            unsigned long long wA = *(const unsigned long long*)&ws[kk][co0 + 64];
            unsigned long long wB = *(const unsigned long long*)&ws[kk][co0 + 128];
#pragma unroll
            for (int i = 0; i < 4; i++) {
                // packed {xv, xv}: single LDS.64 broadcast, no splat movs
                unsigned long long xp =
                    *(const unsigned long long*)&xs2[warp * 4 + i][kk];
                asm("fma.rn.f32x2 %0, %1, %2, %0;" : "+l"(acc2[i][0]) : "l"(xp), "l"(w0));
                asm("fma.rn.f32x2 %0, %1, %2, %0;" : "+l"(acc2[i][1]) : "l"(xp), "l"(wA));
                asm("fma.rn.f32x2 %0, %1, %2, %0;" : "+l"(acc2[i][2]) : "l"(xp), "l"(wB));
            }
        }
        __syncthreads();   // last iteration: also protects the ps aliasing below
    }

    // --- stage acc+bias into smem tile ps[row][col] ---
#pragma unroll
    for (int cp = 0; cp < 3; cp++) {
        int col = co0 + 64 * cp;
        if (cp < 2 || lane < 20) {
            float2 bias = (cp < 2) ? *(const float2*)&b1[col]
                                   : *(const float2*)&b2[co0];
#pragma unroll
            for (int i = 0; i < 4; i++) {
                unsigned int lo, hi;
                asm("mov.b64 {%0, %1}, %2;" : "=r"(lo), "=r"(hi) : "l"(acc2[i][cp]));
                float2 v = make_float2(__uint_as_float(lo) + bias.x,
                                       __uint_as_float(hi) + bias.y);
                *(float2*)&ps[warp * 4 + i][col] = v;
            }
        }
    }
    __syncthreads();

    // --- RoPE + split: pair i -> q=(out1[4i],out1[4i+2]), k=(4i+1,4i+3) ---
#pragma unroll
    for (int it = 0; it < 4; it++) {
        int f   = t + it * 256;
        int r   = f >> 5;
        int i   = f & 31;
        int row = row0 + r;

        float2 tr = strig[f];
        float sn = tr.x, cs = tr.y;

        float4 v = *(const float4*)&ps[r][4 * i];   // q0,k0,q1,k1
        *(float2*)&g_q[row * INNERc + 2 * i] =
            make_float2(v.x * cs - v.z * sn, v.z * cs + v.x * sn);
        *(float2*)&g_k[row * INNERc + 2 * i] =
            make_float2(v.y * cs - v.w * sn, v.w * cs + v.y * sn);
    }

    // --- dense channels: 32 rows x 40, scaled by 0.5 ---
#pragma unroll
    for (int it = 0; it < 5; it++) {
        int f = t + it * 256;
        int r = f / 40, j = f % 40;
        g_d[(row0 + r) * 40 + j] = ps[r][128 + j] * 0.5f;
    }
}

// ---------------------------------------------------------------------------
// Kernel 2: logit expansion + sigmoid. DRAM-write-floor bound (671 MB out).
// One block per (b, mt, nt) 64x64 tile; qk tile in registers, reused across
// L=20 layers; all outputs via streaming STG.128 (__stcs, evict-first).
// ---------------------------------------------------------------------------
__global__ __launch_bounds__(256) void logits_kernel(
    const int* __restrict__ amask, float* __restrict__ out)
{
    __shared__ float qs[64][65];      // [m][d], broadcast reads
    __shared__ float kst[64][64];     // [d][n] transposed
    __shared__ float dms[64][21];     // [m][l] odd channels (2l+1)
    __shared__ float dnst[20][64];    // [l][n] even channels (2l), transposed
    __shared__ float maskM[64];
    __shared__ float maskN[64];

    const int t  = threadIdx.x;
    const int tx = t & 15;
    const int ty = t >> 4;
    const int nt = blockIdx.x, mt = blockIdx.y, b = blockIdx.z;
    const int m0 = mt * 64, n0 = nt * 64;

    {
        const float4* qg = (const float4*)(g_q + (b * Sc + m0) * INNERc);
        const float4* kg = (const float4*)(g_k + (b * Sc + n0) * INNERc);
#pragma unroll
        for (int i = 0; i < 4; i++) {
            int f = t + i * 256;            // 1024 float4s
            int r = f >> 4, d4 = f & 15;
            float4 v = qg[f];
            qs[r][d4 * 4 + 0] = v.x; qs[r][d4 * 4 + 1] = v.y;
            qs[r][d4 * 4 + 2] = v.z; qs[r][d4 * 4 + 3] = v.w;
            v = kg[f];
            kst[d4 * 4 + 0][r] = v.x; kst[d4 * 4 + 1][r] = v.y;
            kst[d4 * 4 + 2][r] = v.z; kst[d4 * 4 + 3][r] = v.w;
        }
    }
#pragma unroll
    for (int i = 0; i < 5; i++) {
        int f = t + i * 256;
        if (f < 64 * 20) {
            int r = f / 20, l = f % 20;
            dms[r][l]  = g_d[(b * Sc + m0 + r) * 40 + 2 * l + 1];
            dnst[l][r] = g_d[(b * Sc + n0 + r) * 40 + 2 * l];
        }
    }
    if (t < 64)            maskM[t]      = (float)amask[b * Sc + m0 + t];
    else if (t < 128)      maskN[t - 64] = (float)amask[b * Sc + n0 + (t - 64)];
    __syncthreads();

    float acc[4][4];
#pragma unroll
    for (int i = 0; i < 4; i++)
#pragma unroll
        for (int j = 0; j < 4; j++) acc[i][j] = 0.f;

#pragma unroll 16
    for (int d = 0; d < 64; d++) {
        float4 kv = *(const float4*)&kst[d][4 * tx];   // LDS.128, conflict-free
        float qv[4];
#pragma unroll
        for (int i = 0; i < 4; i++) qv[i] = qs[ty + 16 * i][d];  // broadcast
#pragma unroll
        for (int i = 0; i < 4; i++) {
            acc[i][0] += qv[i] * kv.x;
            acc[i][1] += qv[i] * kv.y;
            acc[i][2] += qv[i] * kv.z;
            acc[i][3] += qv[i] * kv.w;
        }
    }

    float mmv[4], negmi[4], mnv[4], negmj[4], cz[4][4];
#pragma unroll
    for (int j = 0; j < 4; j++) {
        mnv[j]   = maskN[4 * tx + j];
        negmj[j] = -NEGV * (1.0f - mnv[j]);
    }
#pragma unroll
    for (int i = 0; i < 4; i++) {
        mmv[i]   = maskM[ty + 16 * i];
        negmi[i] = -NEGV * (1.0f - mmv[i]);
#pragma unroll
        for (int j = 0; j < 4; j++) {
            acc[i][j] *= 0.125f;                 // 1/sqrt(64), exact
            int m = m0 + ty + 16 * i, n = n0 + 4 * tx + j;
            cz[i][j] = (m > n) ? -NEGV : 0.0f;
        }
    }

    const int SS    = Sc * Sc;
    const int pbase = b * Lc * SS + (m0 + ty) * Sc + n0 + 4 * tx;
    float* __restrict__ outP = out + NTOT;

    for (int l = 0; l < Lc; l++) {
        float4 dnv = *(const float4*)&dnst[l][4 * tx];  // LDS.128
        float dn[4] = {dnv.x, dnv.y, dnv.z, dnv.w};
        float dmv[4];
#pragma unroll
        for (int i = 0; i < 4; i++) dmv[i] = dms[ty + 16 * i][l];

        int lbase = pbase + l * SS;
#pragma unroll
        for (int i = 0; i < 4; i++) {
            float4 vlog, vprob;
            float* vl = &vlog.x;
            float* vp = &vprob.x;
#pragma unroll
            for (int j = 0; j < 4; j++) {
                // match reference op order: (qk/8 + dq_n) + dk_m
                float v = (acc[i][j] + dn[j]) + dmv[i];
                v = fmaf(v, mmv[i], negmi[i]);   // *m1 - NEG*(1-m1)
                v = fmaf(v, mnv[j], negmj[j]);   // *m2 - NEG*(1-m2)
                v = v + cz[i][j];                // - tril*NEG
                vl[j] = v;
                vp[j] = __fdividef(1.0f, 1.0f + __expf(-v));
            }
            int idx = lbase + i * 16 * Sc;       // multiple of 4 (n0+4tx)
            __stcs((float4*)(out  + idx), vlog);   // streaming STG.128
            __stcs((float4*)(outP + idx), vprob);
        }
    }
}

// ---------------------------------------------------------------------------
extern "C" void kernel_launch(void* const* d_in, const int* in_sizes, int n_in,
                              void* d_out, int out_size)
{
    const float* x   = (const float*)d_in[0];
    const int*   am  = (const int*)  d_in[1];
    const float* w1  = (const float*)d_in[2];
    const float* b1  = (const float*)d_in[3];
    const float* w2  = (const float*)d_in[4];
    const float* b2  = (const float*)d_in[5];
    float* out = (float*)d_out;

    proj_rope_kernel<<<ROWS / 32, 256>>>(x, w1, b1, w2, b2);
    logits_kernel<<<dim3(Sc / 64, Sc / 64, Bc), 256>>>(am, out);
}